// round 10
// baseline (speedup 1.0000x reference)
#include <cuda_runtime.h>
#include <cuda_bf16.h>

#define NREF  4096
#define NIN   8192
#define DFEAT 512
#define PDIM  256

// Swizzled tile: 128 rows x 32 bf16 = 64B/row, no padding.
#define TILE_B   8192                       // 128*64
#define STAGE_B  (4 * TILE_B)               // 32768: Ah, Al, Bh, Bl
#define NSTAGE   3
#define SMEM_TOTAL (NSTAGE * STAGE_B + 512) // 98816

// ---------------- scratch (device globals: allocation-guard safe) ----------
__device__ __nv_bfloat16 g_Xh[NREF * DFEAT];
__device__ __nv_bfloat16 g_Xl[NREF * DFEAT];
__device__ __nv_bfloat16 g_Dh[NIN * DFEAT];
__device__ __nv_bfloat16 g_Dl[NIN * DFEAT];
__device__ __nv_bfloat16 g_Ah[PDIM * NREF];
__device__ __nv_bfloat16 g_Al[PDIM * NREF];
__device__ __nv_bfloat16 g_Kth[(size_t)NIN * NREF];   // K^T hi  [NIN, NREF]
__device__ __nv_bfloat16 g_Ktl[(size_t)NIN * NREF];   // K^T lo
__device__ float g_P[2 * PDIM * NIN];                 // split-K partials (16 MB)

__device__ __forceinline__ unsigned sm32(const void* p) {
    unsigned r;
    asm("{.reg .u64 t; cvta.to.shared.u64 t, %1; cvt.u32.u64 %0, t;}" : "=r"(r) : "l"(p));
    return r;
}

// Load one 128x32 bf16 tile into swizzled smem. 256 threads, 2 chunks each.
__device__ __forceinline__ void load_tile(unsigned sbuf, const __nv_bfloat16* src,
                                          int rowBase, int K, int kOff, int tid) {
    const int row = tid >> 1;
    const int ch0 = (tid & 1) * 2;
    const char* g = (const char*)(src + (size_t)(rowBase + row) * K + kOff) + ch0 * 16;
    const int sw = (row >> 1) & 3;
    const unsigned s0 = sbuf + row * 64 + (((ch0)     ^ sw) << 4);
    const unsigned s1 = sbuf + row * 64 + (((ch0 + 1) ^ sw) << 4);
    asm volatile("cp.async.cg.shared.global [%0], [%1], 16;\n\t"
                 "cp.async.cg.shared.global [%2], [%3], 16;"
                 :: "r"(s0), "l"(g), "r"(s1), "l"(g + 16));
}

__device__ __forceinline__ void mma16(float* c, const unsigned* a, unsigned b0, unsigned b1) {
    asm volatile(
        "mma.sync.aligned.m16n8k16.row.col.f32.bf16.bf16.f32 "
        "{%0,%1,%2,%3}, {%4,%5,%6,%7}, {%8,%9}, {%0,%1,%2,%3};"
        : "+f"(c[0]), "+f"(c[1]), "+f"(c[2]), "+f"(c[3])
        : "r"(a[0]), "r"(a[1]), "r"(a[2]), "r"(a[3]), "r"(b0), "r"(b1));
}

#define LDSM4(r, addr)                                                           \
    asm volatile("ldmatrix.sync.aligned.m8n8.x4.shared.b16 {%0,%1,%2,%3}, [%4];" \
                 : "=r"((r)[0]), "=r"((r)[1]), "=r"((r)[2]), "=r"((r)[3])        \
                 : "r"(addr))

__device__ __forceinline__ unsigned sw_addr(int row, int ch) {
    return row * 64 + ((ch ^ ((row >> 1) & 3)) << 4);
}

// One BLK_K=32 stage (32x64 warp tile), fused 3-term split accumulation:
//   c += Ah.Bh + Ah.Bl + Al.Bh
// B fragments double-buffered: group g+1's LDSMs issue before group g's MMAs,
// hiding the shared-memory latency under tensor-pipe execution.
__device__ __forceinline__ void compute3_k32(unsigned sAh, unsigned sAl,
                                             unsigned sBh, unsigned sBl,
                                             int warpM, int warpN, int lane,
                                             float (*c)[8][4]) {
    const int ra  = warpM * 32 + (lane & 15);
    const int rb  = warpN * 64 + (lane & 7) + ((lane >> 4) & 1) * 8;
    const int cha = (lane >> 4) & 1;
    const int chb = (lane >> 3) & 1;

    unsigned bh[2][4], bl[2][4];
    // preload g=0 of kk-half 0
    {
        const unsigned boff = sw_addr(rb, chb);
        LDSM4(bh[0], sBh + boff);
        LDSM4(bl[0], sBl + boff);
    }
#pragma unroll
    for (int kk2 = 0; kk2 < 2; kk2++) {
        const int chk = kk2 * 2;
        unsigned ah[2][4], al[2][4];
#pragma unroll
        for (int mi = 0; mi < 2; mi++) {
            const unsigned off = sw_addr(ra + mi * 16, chk + cha);
            LDSM4(ah[mi], sAh + off);
            LDSM4(al[mi], sAl + off);
        }
#pragma unroll
        for (int g = 0; g < 4; g++) {
            const int cur = g & 1, nxt = cur ^ 1;
            if (g < 3) {
                const unsigned boff = sw_addr(rb + (g + 1) * 16, chk + chb);
                LDSM4(bh[nxt], sBh + boff);
                LDSM4(bl[nxt], sBl + boff);
            } else if (kk2 == 0) {
                const unsigned boff = sw_addr(rb, 2 + chb);
                LDSM4(bh[nxt], sBh + boff);
                LDSM4(bl[nxt], sBl + boff);
            }
            mma16(c[0][2 * g],     ah[0], bh[cur][0], bh[cur][1]);
            mma16(c[0][2 * g + 1], ah[0], bh[cur][2], bh[cur][3]);
            mma16(c[1][2 * g],     ah[1], bh[cur][0], bh[cur][1]);
            mma16(c[1][2 * g + 1], ah[1], bh[cur][2], bh[cur][3]);
            mma16(c[0][2 * g],     ah[0], bl[cur][0], bl[cur][1]);
            mma16(c[0][2 * g + 1], ah[0], bl[cur][2], bl[cur][3]);
            mma16(c[1][2 * g],     ah[1], bl[cur][0], bl[cur][1]);
            mma16(c[1][2 * g + 1], ah[1], bl[cur][2], bl[cur][3]);
            mma16(c[0][2 * g],     al[0], bh[cur][0], bh[cur][1]);
            mma16(c[0][2 * g + 1], al[0], bh[cur][2], bh[cur][3]);
            mma16(c[1][2 * g],     al[1], bh[cur][0], bh[cur][1]);
            mma16(c[1][2 * g + 1], al[1], bh[cur][2], bh[cur][3]);
        }
    }
}

// ---------------------------------------------------------------------------
// GEMM1 (transposed): Kt[j,i] = mask(Z[j]==Z_ref[i]) * (desc[j].X_ref[i])^expK
// 3-stage cp.async pipeline, ONE __syncthreads per K32 iteration.
// ---------------------------------------------------------------------------
__global__ __launch_bounds__(256, 2) void gemm1_mma(const int* __restrict__ Zq,
                                                    const int* __restrict__ Zx,
                                                    const int* __restrict__ expKp) {
    extern __shared__ char dynsm[];
    const int tid = threadIdx.x, lane = tid & 31, wid = tid >> 5;
    const int warpM = wid & 3, warpN = wid >> 2;
    const int jBase = blockIdx.y * 128, iBase = blockIdx.x * 128;

    int* Zcol = (int*)(dynsm + NSTAGE * STAGE_B);
    if (tid < 128) Zcol[tid] = Zx[iBase + tid];

    float c[2][8][4];
#pragma unroll
    for (int i = 0; i < 2; i++)
#pragma unroll
        for (int j = 0; j < 8; j++)
#pragma unroll
            for (int k = 0; k < 4; k++) c[i][j][k] = 0.0f;

    unsigned st[NSTAGE][4];
#pragma unroll
    for (int s = 0; s < NSTAGE; s++)
#pragma unroll
        for (int t = 0; t < 4; t++)
            st[s][t] = sm32(dynsm + s * STAGE_B + t * TILE_B);

#pragma unroll
    for (int s = 0; s < 2; s++) {
        load_tile(st[s][0], g_Dh, jBase, DFEAT, s * 32, tid);
        load_tile(st[s][1], g_Dl, jBase, DFEAT, s * 32, tid);
        load_tile(st[s][2], g_Xh, iBase, DFEAT, s * 32, tid);
        load_tile(st[s][3], g_Xl, iBase, DFEAT, s * 32, tid);
        asm volatile("cp.async.commit_group;" ::: "memory");
    }

    const int NITER = DFEAT / 32;       // 16
    for (int it = 0; it < NITER; it++) {
        asm volatile("cp.async.wait_group 1;" ::: "memory");
        __syncthreads();
        if (it + 2 < NITER) {
            const int s = (it + 2) % NSTAGE, kOff = (it + 2) * 32;
            load_tile(st[s][0], g_Dh, jBase, DFEAT, kOff, tid);
            load_tile(st[s][1], g_Dl, jBase, DFEAT, kOff, tid);
            load_tile(st[s][2], g_Xh, iBase, DFEAT, kOff, tid);
            load_tile(st[s][3], g_Xl, iBase, DFEAT, kOff, tid);
        }
        asm volatile("cp.async.commit_group;" ::: "memory");
        const int b = it % NSTAGE;
        compute3_k32(st[b][0], st[b][1], st[b][2], st[b][3], warpM, warpN, lane, c);
    }

    // epilogue: pow, mask, bf16 hi/lo split, store K^T
    const int e = expKp[0];
#pragma unroll
    for (int mi = 0; mi < 2; mi++) {
        const int r0 = jBase + warpM * 32 + mi * 16 + (lane >> 2);
        const int zr0 = Zq[r0], zr1 = Zq[r0 + 8];
        const size_t ro0 = (size_t)r0 * NREF, ro1 = (size_t)(r0 + 8) * NREF;
#pragma unroll
        for (int ni = 0; ni < 8; ni++) {
            const int colL = warpN * 64 + ni * 8 + 2 * (lane & 3);
            const int zc0 = Zcol[colL], zc1 = Zcol[colL + 1];
            float v0 = c[mi][ni][0], v1 = c[mi][ni][1];
            float v2 = c[mi][ni][2], v3 = c[mi][ni][3];
            float p0 = 1.f, p1 = 1.f, p2 = 1.f, p3 = 1.f;
            for (int t = 0; t < e; t++) { p0 *= v0; p1 *= v1; p2 *= v2; p3 *= v3; }
            if (zr0 != zc0) p0 = 0.f;
            if (zr0 != zc1) p1 = 0.f;
            if (zr1 != zc0) p2 = 0.f;
            if (zr1 != zc1) p3 = 0.f;

            __nv_bfloat16 h0 = __float2bfloat16(p0), h1 = __float2bfloat16(p1);
            __nv_bfloat16 h2 = __float2bfloat16(p2), h3 = __float2bfloat16(p3);
            __nv_bfloat162 hh01, hh23, ll01, ll23;
            hh01.x = h0; hh01.y = h1;
            hh23.x = h2; hh23.y = h3;
            ll01.x = __float2bfloat16(p0 - __bfloat162float(h0));
            ll01.y = __float2bfloat16(p1 - __bfloat162float(h1));
            ll23.x = __float2bfloat16(p2 - __bfloat162float(h2));
            ll23.y = __float2bfloat16(p3 - __bfloat162float(h3));

            const size_t cg = (size_t)iBase + colL;
            *(__nv_bfloat162*)(g_Kth + ro0 + cg) = hh01;
            *(__nv_bfloat162*)(g_Kth + ro1 + cg) = hh23;
            *(__nv_bfloat162*)(g_Ktl + ro0 + cg) = ll01;
            *(__nv_bfloat162*)(g_Ktl + ro1 + cg) = ll23;
        }
    }
}

// ---------------------------------------------------------------------------
// GEMM2 split-K: P[z][p,j] = Alpha[p, zK..] . Kt[j, zK..]   (128x128 tile)
// grid (64, 2, 2) = 256 CTAs, 3-stage pipeline, one barrier per iteration.
// ---------------------------------------------------------------------------
__global__ __launch_bounds__(256, 2) void gemm2_mma(void) {
    extern __shared__ char dynsm[];
    const int tid = threadIdx.x, lane = tid & 31, wid = tid >> 5;
    const int warpM = wid & 3, warpN = wid >> 2;
    const int pBase = blockIdx.y * 128, jBase = blockIdx.x * 128;
    const int kBase = blockIdx.z * (NREF / 2);
    float* P = g_P + (size_t)blockIdx.z * PDIM * NIN;

    float c[2][8][4];
#pragma unroll
    for (int i = 0; i < 2; i++)
#pragma unroll
        for (int j = 0; j < 8; j++)
#pragma unroll
            for (int k = 0; k < 4; k++) c[i][j][k] = 0.0f;

    unsigned st[NSTAGE][4];
#pragma unroll
    for (int s = 0; s < NSTAGE; s++)
#pragma unroll
        for (int t = 0; t < 4; t++)
            st[s][t] = sm32(dynsm + s * STAGE_B + t * TILE_B);

#pragma unroll
    for (int s = 0; s < 2; s++) {
        const int kOff = kBase + s * 32;
        load_tile(st[s][0], g_Ah, pBase, NREF, kOff, tid);
        load_tile(st[s][1], g_Al, pBase, NREF, kOff, tid);
        load_tile(st[s][2], g_Kth, jBase, NREF, kOff, tid);
        load_tile(st[s][3], g_Ktl, jBase, NREF, kOff, tid);
        asm volatile("cp.async.commit_group;" ::: "memory");
    }

    const int NITER = (NREF / 2) / 32;  // 64
    for (int it = 0; it < NITER; it++) {
        asm volatile("cp.async.wait_group 1;" ::: "memory");
        __syncthreads();
        if (it + 2 < NITER) {
            const int s = (it + 2) % NSTAGE, kOff = kBase + (it + 2) * 32;
            load_tile(st[s][0], g_Ah, pBase, NREF, kOff, tid);
            load_tile(st[s][1], g_Al, pBase, NREF, kOff, tid);
            load_tile(st[s][2], g_Kth, jBase, NREF, kOff, tid);
            load_tile(st[s][3], g_Ktl, jBase, NREF, kOff, tid);
        }
        asm volatile("cp.async.commit_group;" ::: "memory");
        const int b = it % NSTAGE;
        compute3_k32(st[b][0], st[b][1], st[b][2], st[b][3], warpM, warpN, lane, c);
    }

#pragma unroll
    for (int mi = 0; mi < 2; mi++) {
        const int r0 = pBase + warpM * 32 + mi * 16 + (lane >> 2);
        const size_t ro0 = (size_t)r0 * NIN, ro1 = (size_t)(r0 + 8) * NIN;
#pragma unroll
        for (int ni = 0; ni < 8; ni++) {
            const int col = jBase + warpN * 64 + ni * 8 + 2 * (lane & 3);
            *(float2*)(P + ro0 + col) = make_float2(c[mi][ni][0], c[mi][ni][1]);
            *(float2*)(P + ro1 + col) = make_float2(c[mi][ni][2], c[mi][ni][3]);
        }
    }
}

// Reduce the two split-K partials into the output.
__global__ void reduceY(float* __restrict__ Y) {
    int i = blockIdx.x * blockDim.x + threadIdx.x;
    const int n4 = PDIM * NIN / 4;
    if (i < n4) {
        float4 a = ((const float4*)g_P)[i];
        float4 b = ((const float4*)(g_P + PDIM * NIN))[i];
        ((float4*)Y)[i] = make_float4(a.x + b.x, a.y + b.y, a.z + b.z, a.w + b.w);
    }
}

// ---------------------------------------------------------------------------
// fp32 -> bf16 hi/lo splits
// ---------------------------------------------------------------------------
__device__ __forceinline__ void split2(float2 v, __nv_bfloat162* hp, __nv_bfloat162* lp, int i) {
    __nv_bfloat16 h0 = __float2bfloat16(v.x), h1 = __float2bfloat16(v.y);
    __nv_bfloat162 hh, ll;
    hh.x = h0; hh.y = h1;
    ll.x = __float2bfloat16(v.x - __bfloat162float(h0));
    ll.y = __float2bfloat16(v.y - __bfloat162float(h1));
    hp[i] = hh; lp[i] = ll;
}
__global__ void split_X(const float* __restrict__ x) {
    int i = blockIdx.x * blockDim.x + threadIdx.x;
    if (i < NREF * DFEAT / 2)
        split2(((const float2*)x)[i], (__nv_bfloat162*)g_Xh, (__nv_bfloat162*)g_Xl, i);
}
__global__ void split_D(const float* __restrict__ x) {
    int i = blockIdx.x * blockDim.x + threadIdx.x;
    if (i < NIN * DFEAT / 2)
        split2(((const float2*)x)[i], (__nv_bfloat162*)g_Dh, (__nv_bfloat162*)g_Dl, i);
}
__global__ void split_A(const float* __restrict__ x) {
    int i = blockIdx.x * blockDim.x + threadIdx.x;
    if (i < PDIM * NREF / 2)
        split2(((const float2*)x)[i], (__nv_bfloat162*)g_Ah, (__nv_bfloat162*)g_Al, i);
}

extern "C" void kernel_launch(void* const* d_in, const int* in_sizes, int n_in,
                              void* d_out, int out_size) {
    const float* Alpha = (const float*)d_in[0];
    const float* X_ref = (const float*)d_in[1];
    const float* desc  = (const float*)d_in[2];
    const int*   Z_ref = (const int*)d_in[3];
    const int*   Z     = (const int*)d_in[4];
    const int*   expK  = (const int*)d_in[5];
    float* Y = (float*)d_out;

    cudaFuncSetAttribute(gemm1_mma, cudaFuncAttributeMaxDynamicSharedMemorySize, SMEM_TOTAL);
    cudaFuncSetAttribute(gemm2_mma, cudaFuncAttributeMaxDynamicSharedMemorySize, SMEM_TOTAL);

    split_X<<<(NREF * DFEAT / 2 + 255) / 256, 256>>>(X_ref);
    split_D<<<(NIN * DFEAT / 2 + 255) / 256, 256>>>(desc);
    split_A<<<(PDIM * NREF / 2 + 255) / 256, 256>>>(Alpha);

    gemm1_mma<<<dim3(NREF / 128, NIN / 128), 256, SMEM_TOTAL>>>(Z, Z_ref, expK);
    gemm2_mma<<<dim3(NIN / 128, PDIM / 128, 2), 256, SMEM_TOTAL>>>();
    reduceY<<<(PDIM * NIN / 4 + 255) / 256, 256>>>(Y);
}